// round 15
// baseline (speedup 1.0000x reference)
#include <cuda_runtime.h>
#include <cstdint>

namespace {

constexpr int NUM_HEADS = 14;
constexpr int BROWS  = 1024;
constexpr int DIN    = 1920;
constexpr int DSLICE = 128;
constexpr int HID    = NUM_HEADS * DSLICE;   // 1792
constexpr int PMAX   = 36928;

constexpr int BM = 128, BK = 32;
constexpr int SST = BK + 4;

__constant__ int c_p[NUM_HEADS] =
    {9280,18496,36928,36928,36928,36928,36928,36928,36928,18496,9280,18496,18496,9280};
__constant__ int c_tile_start[NUM_HEADS] =
    {0,73,218,507,796,1085,1374,1663,1952,2241,2386,2459,2604,2749};
__constant__ int c_cum[NUM_HEADS] =
    {0,9280,27776,64704,101632,138560,175488,212416,249344,286272,304768,314048,332544,351040};

constexpr int TOTAL_NTILES = 2822;
constexpr int HEAD_SPLIT   = 1663;           // c_tile_start[7] -> heads 0-6 | 7-13
constexpr int MTILES = BROWS / BM;           // 8

constexpr int TILE_FLOATS = BM * DSLICE;     // 16384 floats = 64KB per tile

// head smem: B 64KB + A double-buffer 2x64KB
constexpr size_t HEAD_SMEM_BYTES = (size_t)(3 * TILE_FLOATS) * sizeof(float); // 196608

// hidden activations in A-FRAGMENT-MAJOR 128-row tiles: [head][mtile][16384]
__device__ float g_hfrag[(size_t)NUM_HEADS * MTILES * TILE_FLOATS];

__device__ __forceinline__ uint32_t f2tf32(float f) {
    uint32_t r;
    asm("cvt.rna.tf32.f32 %0, %1;" : "=r"(r) : "f"(f));
    return r;
}

__device__ __forceinline__ void mma_tf32(float* c, const uint32_t* a, const uint32_t* b) {
    asm volatile(
        "mma.sync.aligned.m16n8k8.row.col.f32.tf32.tf32.f32 "
        "{%0,%1,%2,%3}, {%4,%5,%6,%7}, {%8,%9}, {%0,%1,%2,%3};\n"
        : "+f"(c[0]), "+f"(c[1]), "+f"(c[2]), "+f"(c[3])
        : "r"(a[0]), "r"(a[1]), "r"(a[2]), "r"(a[3]),
          "r"(b[0]), "r"(b[1]));
}

__device__ __forceinline__ void cp_async16_s(uint32_t dst_smem, const float* src) {
    asm volatile("cp.async.cg.shared.global [%0], [%1], 16;\n" :: "r"(dst_smem), "l"(src));
}

// A-fragment-major float index within a 128x128 tile (R6 layout, verified).
__device__ __forceinline__ int afrag_idx(int m, int k) {
    int rb = m >> 4, m16 = m & 15, lr = m16 & 7, er = m16 >> 3;
    int kstep = k >> 3, k8 = k & 7, la3 = k8 & 3, ec = k8 >> 2;
    return ((((kstep << 3) + rb) * 32 + (lr << 2) + la3) << 2) + er + (ec << 1);
}

// B-fragment-major float index within a 128(out-col)x128(k) tile (R6 layout, verified).
__device__ __forceinline__ int bfrag_idx(int row, int k) {
    int wn = row >> 6, j = (row & 63) >> 3, lr = row & 7;
    int kstep = k >> 3, la3 = k & 3, b1 = ((k & 7) >= 4);
    return (((((kstep << 1) + wn) << 2) + (j >> 1)) * 32 + (lr << 2) + la3) * 4
           + ((j & 1) << 1) + b1;
}

// ---------------------------------------------------------------------------
// Kernel A (R14-verbatim + nt64 base): hidden = relu(x @ Wh^T + bh),
//   tf32-rounded, A-fragment-major scatter. 64x64 tiles, 128 threads.
// ---------------------------------------------------------------------------
__global__ void __launch_bounds__(128)
hidden_gemm(const float* __restrict__ x,
            const float* __restrict__ Wh,
            const float* __restrict__ bh,
            int nt64_base)
{
    __shared__ float As[64][SST];
    __shared__ float Bs[64][SST];

    const int mtile16 = blockIdx.x & 15;      // 0..15 (64-row tiles)
    const int nt64    = nt64_base + (blockIdx.x >> 4);
    const int m0 = mtile16 * 64;
    const int n0 = nt64 * 64;

    const int tid  = threadIdx.x;
    const int lane = tid & 31;
    const int warp = tid >> 5;                // 0..3
    const int wm = warp >> 1;                 // 0..1 (32 rows)
    const int wn = warp & 1;                  // 0..1 (32 cols)

    float acc[2][4][4];
    #pragma unroll
    for (int t = 0; t < 2; ++t)
        #pragma unroll
        for (int j = 0; j < 4; ++j)
            #pragma unroll
            for (int q = 0; q < 4; ++q) acc[t][j][q] = 0.f;

    // register staging for the K pipeline (4 A-vec4 + 4 B-vec4 per thread)
    float4 ra[4], rb[4];
    #pragma unroll
    for (int it = 0; it < 4; ++it) {
        int slot = tid + it * 128;            // 0..511
        int r  = slot >> 3;                   // 0..63
        int c4 = (slot & 7) * 4;
        ra[it] = *reinterpret_cast<const float4*>(x  + (size_t)(m0 + r) * DIN + c4);
        rb[it] = *reinterpret_cast<const float4*>(Wh + (size_t)(n0 + r) * DIN + c4);
    }

    for (int k0 = 0; k0 < DIN; k0 += BK) {
        #pragma unroll
        for (int it = 0; it < 4; ++it) {
            int slot = tid + it * 128;
            int r  = slot >> 3;
            int c4 = (slot & 7) * 4;
            As[r][c4 + 0] = __uint_as_float(f2tf32(ra[it].x));
            As[r][c4 + 1] = __uint_as_float(f2tf32(ra[it].y));
            As[r][c4 + 2] = __uint_as_float(f2tf32(ra[it].z));
            As[r][c4 + 3] = __uint_as_float(f2tf32(ra[it].w));
            Bs[r][c4 + 0] = __uint_as_float(f2tf32(rb[it].x));
            Bs[r][c4 + 1] = __uint_as_float(f2tf32(rb[it].y));
            Bs[r][c4 + 2] = __uint_as_float(f2tf32(rb[it].z));
            Bs[r][c4 + 3] = __uint_as_float(f2tf32(rb[it].w));
        }
        __syncthreads();

        // issue next K-slab's LDGs; they drain under the MMA block
        if (k0 + BK < DIN) {
            #pragma unroll
            for (int it = 0; it < 4; ++it) {
                int slot = tid + it * 128;
                int r  = slot >> 3;
                int c4 = (slot & 7) * 4;
                ra[it] = *reinterpret_cast<const float4*>(
                    x + (size_t)(m0 + r) * DIN + k0 + BK + c4);
                rb[it] = *reinterpret_cast<const float4*>(
                    Wh + (size_t)(n0 + r) * DIN + k0 + BK + c4);
            }
        }

        #pragma unroll
        for (int ks = 0; ks < BK; ks += 8) {
            uint32_t a[2][4];
            #pragma unroll
            for (int t = 0; t < 2; ++t) {
                int row = wm * 32 + t * 16 + (lane >> 2);
                int kc  = ks + (lane & 3);
                a[t][0] = __float_as_uint(As[row][kc]);
                a[t][1] = __float_as_uint(As[row + 8][kc]);
                a[t][2] = __float_as_uint(As[row][kc + 4]);
                a[t][3] = __float_as_uint(As[row + 8][kc + 4]);
            }
            #pragma unroll
            for (int j = 0; j < 4; ++j) {
                int col = wn * 32 + j * 8 + (lane >> 2);
                int kc  = ks + (lane & 3);
                uint32_t b[2];
                b[0] = __float_as_uint(Bs[col][kc]);
                b[1] = __float_as_uint(Bs[col][kc + 4]);
                mma_tf32(acc[0][j], a[0], b);
                mma_tf32(acc[1][j], a[1], b);
            }
        }
        __syncthreads();
    }

    // Epilogue: bias + relu + tf32 round -> A-fragment-major scatter.
    const int head  = nt64 >> 1;
    const int kh    = (nt64 & 1) * 64;          // k-offset within head slice
    const int mt128 = mtile16 >> 1;
    const int rbase = (mtile16 & 1) * 64;       // row base within 128-row tile
    float* Hf = g_hfrag + ((size_t)head * MTILES + mt128) * TILE_FLOATS;
    const int lr2  = lane >> 2;
    const int la32 = lane & 3;
    #pragma unroll
    for (int t = 0; t < 2; ++t) {
        #pragma unroll
        for (int j = 0; j < 4; ++j) {
            int klocal = wn * 32 + j * 8 + 2 * la32;   // 0..63
            float b0 = bh[n0 + klocal], b1 = bh[n0 + klocal + 1];
            int kbase = kh + klocal;                   // 0..127
            int mA = rbase + wm * 32 + t * 16 + lr2;   // 0..127
            Hf[afrag_idx(mA,     kbase    )] =
                __uint_as_float(f2tf32(fmaxf(acc[t][j][0] + b0, 0.f)));
            Hf[afrag_idx(mA,     kbase + 1)] =
                __uint_as_float(f2tf32(fmaxf(acc[t][j][1] + b1, 0.f)));
            Hf[afrag_idx(mA + 8, kbase    )] =
                __uint_as_float(f2tf32(fmaxf(acc[t][j][2] + b0, 0.f)));
            Hf[afrag_idx(mA + 8, kbase + 1)] =
                __uint_as_float(f2tf32(fmaxf(acc[t][j][3] + b1, 0.f)));
        }
    }
}

// ---------------------------------------------------------------------------
// Kernel B (R6/R12 verbatim + ntg base): 256 threads, warp tile 32x64, one
//   CTA per 128-col N-tile, 8 M-tiles. B fragment-major resident; A tiles
//   cp.async double-buffered; 1-deep register pipeline.
// ---------------------------------------------------------------------------
__global__ void __launch_bounds__(256)
head_gemm(const float* __restrict__ Wheads,
          const float* __restrict__ bheads,
          float* __restrict__ out,
          int ntg_base)
{
    extern __shared__ float smem[];
    float* sB = smem;                         // 16384 floats
    float* sA = smem + TILE_FLOATS;           // 2 x 16384 floats

    const int ntg = ntg_base + blockIdx.x;
    int h = 0;
    #pragma unroll
    for (int i = 1; i < NUM_HEADS; ++i) h += (ntg >= c_tile_start[i]);
    const int ntile = ntg - c_tile_start[h];
    const int p  = c_p[h];
    const int n0 = ntile * 128;

    const float* Bg    = Wheads + (size_t)h * PMAX * DSLICE;
    const float* bias  = bheads + (size_t)h * PMAX;
    float* Og = out + (size_t)c_cum[h] * BROWS;
    const float* Hf = g_hfrag + (size_t)h * MTILES * TILE_FLOATS;

    const int tid  = threadIdx.x;
    const int lane = tid & 31;
    const int warp = tid >> 5;
    const int wm = warp >> 1;   // 0..3
    const int wn = warp & 1;    // 0..1
    const int la3 = lane & 3;
    const int lr  = lane >> 2;

    const uint32_t sA_u = (uint32_t)__cvta_generic_to_shared(sA);

    // prefetch A tile 0 (contiguous 64KB)
    #pragma unroll
    for (int it = 0; it < 16; ++it) {
        int fo = (it * 256 + tid) * 4;
        cp_async16_s(sA_u + fo * 4, Hf + fo);
    }
    asm volatile("cp.async.commit_group;\n");

    // load B tile once -> fragment-major smem
    #pragma unroll
    for (int it = 0; it < 16; ++it) {
        int slot = it * 256 + tid;
        int row = slot >> 5;
        int k4  = (slot & 31) * 4;
        float4 v;
        if (n0 + row < p) {
            v = *reinterpret_cast<const float4*>(Bg + (size_t)(n0 + row) * DSLICE + k4);
        } else {
            v = make_float4(0.f, 0.f, 0.f, 0.f);
        }
        sB[bfrag_idx(row, k4    )] = __uint_as_float(f2tf32(v.x));
        sB[bfrag_idx(row, k4 + 1)] = __uint_as_float(f2tf32(v.y));
        sB[bfrag_idx(row, k4 + 2)] = __uint_as_float(f2tf32(v.z));
        sB[bfrag_idx(row, k4 + 3)] = __uint_as_float(f2tf32(v.w));
    }

    // hoist bias (same columns for every M-tile)
    float bs0[8], bs1[8];
    #pragma unroll
    for (int j = 0; j < 8; ++j) {
        int col = n0 + wn * 64 + j * 8 + 2 * la3;
        bs0[j] = (col < p) ? bias[col]     : 0.f;
        bs1[j] = (col < p) ? bias[col + 1] : 0.f;
    }

    const float4* sB4 = reinterpret_cast<const float4*>(sB);

    asm volatile("cp.async.wait_group 0;\n" ::: "memory");
    __syncthreads();

    for (int mt = 0; mt < MTILES; ++mt) {
        // prefetch next A tile into the other buffer
        if (mt + 1 < MTILES) {
            const float* src = Hf + (size_t)(mt + 1) * TILE_FLOATS;
            uint32_t dst = sA_u + (uint32_t)(((mt + 1) & 1) ? TILE_FLOATS * 4 : 0);
            #pragma unroll
            for (int it = 0; it < 16; ++it) {
                int fo = (it * 256 + tid) * 4;
                cp_async16_s(dst + fo * 4, src + fo);
            }
            asm volatile("cp.async.commit_group;\n");
        }

        const float4* sA4 = reinterpret_cast<const float4*>(
            sA + (mt & 1) * TILE_FLOATS);

        float acc[2][8][4];
        #pragma unroll
        for (int t = 0; t < 2; ++t)
            #pragma unroll
            for (int j = 0; j < 8; ++j)
                #pragma unroll
                for (int q = 0; q < 4; ++q) acc[t][j][q] = 0.f;

        // register pipeline: fragments for kstep, prefetch kstep+1
        float4 a_cur[2], a_nxt[2], b_cur[2], b_nxt[2], b_cur2[2], b_nxt2[2];
        #pragma unroll
        for (int t = 0; t < 2; ++t)
            a_cur[t] = sA4[(wm * 2 + t) * 32 + lane];
        b_cur[0]  = sB4[(wn * 4 + 0) * 32 + lane];
        b_cur[1]  = sB4[(wn * 4 + 1) * 32 + lane];
        b_cur2[0] = sB4[(wn * 4 + 2) * 32 + lane];
        b_cur2[1] = sB4[(wn * 4 + 3) * 32 + lane];

        #pragma unroll
        for (int ks = 0; ks < 16; ++ks) {
            if (ks + 1 < 16) {
                #pragma unroll
                for (int t = 0; t < 2; ++t)
                    a_nxt[t] = sA4[((ks + 1) * 8 + wm * 2 + t) * 32 + lane];
                b_nxt[0]  = sB4[(((ks + 1) * 2 + wn) * 4 + 0) * 32 + lane];
                b_nxt[1]  = sB4[(((ks + 1) * 2 + wn) * 4 + 1) * 32 + lane];
                b_nxt2[0] = sB4[(((ks + 1) * 2 + wn) * 4 + 2) * 32 + lane];
                b_nxt2[1] = sB4[(((ks + 1) * 2 + wn) * 4 + 3) * 32 + lane];
            }
            const uint32_t* au[2] = {
                reinterpret_cast<const uint32_t*>(&a_cur[0]),
                reinterpret_cast<const uint32_t*>(&a_cur[1])};
            #pragma unroll
            for (int jp = 0; jp < 2; ++jp) {
                const uint32_t* bp = reinterpret_cast<const uint32_t*>(&b_cur[jp]);
                uint32_t b0[2] = {bp[0], bp[1]};
                uint32_t b1[2] = {bp[2], bp[3]};
                mma_tf32(acc[0][jp * 2],     au[0], b0);
                mma_tf32(acc[1][jp * 2],     au[1], b0);
                mma_tf32(acc[0][jp * 2 + 1], au[0], b1);
                mma_tf32(acc[1][jp * 2 + 1], au[1], b1);
            }
            #pragma unroll
            for (int jp = 0; jp < 2; ++jp) {
                const uint32_t* bp = reinterpret_cast<const uint32_t*>(&b_cur2[jp]);
                uint32_t b0[2] = {bp[0], bp[1]};
                uint32_t b1[2] = {bp[2], bp[3]};
                mma_tf32(acc[0][4 + jp * 2],     au[0], b0);
                mma_tf32(acc[1][4 + jp * 2],     au[1], b0);
                mma_tf32(acc[0][4 + jp * 2 + 1], au[0], b1);
                mma_tf32(acc[1][4 + jp * 2 + 1], au[1], b1);
            }
            a_cur[0] = a_nxt[0]; a_cur[1] = a_nxt[1];
            b_cur[0] = b_nxt[0]; b_cur[1] = b_nxt[1];
            b_cur2[0] = b_nxt2[0]; b_cur2[1] = b_nxt2[1];
        }

        // epilogue
        const int m0 = mt * BM;
        #pragma unroll
        for (int t = 0; t < 2; ++t) {
            int row = m0 + wm * 32 + t * 16 + lr;
            #pragma unroll
            for (int j = 0; j < 8; ++j) {
                int col = n0 + wn * 64 + j * 8 + 2 * la3;
                if (col < p) {
                    float2 v0 = make_float2(acc[t][j][0] + bs0[j], acc[t][j][1] + bs1[j]);
                    float2 v1 = make_float2(acc[t][j][2] + bs0[j], acc[t][j][3] + bs1[j]);
                    *reinterpret_cast<float2*>(&Og[(size_t)row * p + col])       = v0;
                    *reinterpret_cast<float2*>(&Og[(size_t)(row + 8) * p + col]) = v1;
                }
            }
        }

        // A(mt+1) ready before next compute; sync also protects buffer reuse
        asm volatile("cp.async.wait_group 0;\n" ::: "memory");
        __syncthreads();
    }
}

} // anonymous namespace

extern "C" void kernel_launch(void* const* d_in, const int* in_sizes, int n_in,
                              void* d_out, int out_size) {
    (void)in_sizes; (void)n_in; (void)out_size;
    const float* x      = (const float*)d_in[0];
    const float* Wh     = (const float*)d_in[1];
    const float* bh     = (const float*)d_in[2];
    const float* Wheads = (const float*)d_in[3];
    const float* bheads = (const float*)d_in[4];
    float* out = (float*)d_out;

    static cudaStream_t s2 = nullptr;
    static cudaEvent_t evA = nullptr, evC = nullptr;
    if (!s2) {
        cudaFuncSetAttribute(head_gemm,
                             cudaFuncAttributeMaxDynamicSharedMemorySize,
                             (int)HEAD_SMEM_BYTES);
        cudaStreamCreateWithFlags(&s2, cudaStreamNonBlocking);
        cudaEventCreateWithFlags(&evA, cudaEventDisableTiming);
        cudaEventCreateWithFlags(&evC, cudaEventDisableTiming);
    }

    // stream 0: hidden part0 (heads 0-6) -> evA -> hidden part1 (heads 7-13)
    hidden_gemm<<<224, 128>>>(x, Wh, bh, 0);
    cudaEventRecord(evA, 0);
    hidden_gemm<<<224, 128>>>(x, Wh, bh, 14);

    // s2: after part0, head tiles of heads 0-6 (overlaps hidden part1)
    cudaStreamWaitEvent(s2, evA, 0);
    head_gemm<<<HEAD_SPLIT, 256, HEAD_SMEM_BYTES, s2>>>(Wheads, bheads, out, 0);
    cudaEventRecord(evC, s2);

    // stream 0: head tiles of heads 7-13 (after hidden part1, concurrent with s2)
    head_gemm<<<TOTAL_NTILES - HEAD_SPLIT, 256, HEAD_SMEM_BYTES>>>(
        Wheads, bheads, out, HEAD_SPLIT);

    // join fork back into the capture-origin stream
    cudaStreamWaitEvent(0, evC, 0);
}

// round 16
// speedup vs baseline: 1.0219x; 1.0219x over previous
#include <cuda_runtime.h>
#include <cstdint>

namespace {

constexpr int NUM_HEADS = 14;
constexpr int BROWS  = 1024;
constexpr int DIN    = 1920;
constexpr int DSLICE = 128;
constexpr int HID    = NUM_HEADS * DSLICE;   // 1792
constexpr int PMAX   = 36928;

constexpr int BM = 128, BK = 32;
constexpr int SST = BK + 4;

__constant__ int c_p[NUM_HEADS] =
    {9280,18496,36928,36928,36928,36928,36928,36928,36928,18496,9280,18496,18496,9280};
__constant__ int c_tile_start[NUM_HEADS] =
    {0,73,218,507,796,1085,1374,1663,1952,2241,2386,2459,2604,2749};
__constant__ int c_cum[NUM_HEADS] =
    {0,9280,27776,64704,101632,138560,175488,212416,249344,286272,304768,314048,332544,351040};

constexpr int TOTAL_NTILES = 2822;
constexpr int MTILES = BROWS / BM;           // 8

constexpr int TILE_FLOATS = BM * DSLICE;     // 16384 floats = 64KB per tile

// head smem: B 64KB + A double-buffer 2x64KB
constexpr size_t HEAD_SMEM_BYTES = (size_t)(3 * TILE_FLOATS) * sizeof(float); // 196608

// hidden activations in A-FRAGMENT-MAJOR 128-row tiles: [head][mtile][16384]
__device__ float g_hfrag[(size_t)NUM_HEADS * MTILES * TILE_FLOATS];

__device__ __forceinline__ uint32_t f2tf32(float f) {
    uint32_t r;
    asm("cvt.rna.tf32.f32 %0, %1;" : "=r"(r) : "f"(f));
    return r;
}

__device__ __forceinline__ void mma_tf32(float* c, const uint32_t* a, const uint32_t* b) {
    asm volatile(
        "mma.sync.aligned.m16n8k8.row.col.f32.tf32.tf32.f32 "
        "{%0,%1,%2,%3}, {%4,%5,%6,%7}, {%8,%9}, {%0,%1,%2,%3};\n"
        : "+f"(c[0]), "+f"(c[1]), "+f"(c[2]), "+f"(c[3])
        : "r"(a[0]), "r"(a[1]), "r"(a[2]), "r"(a[3]),
          "r"(b[0]), "r"(b[1]));
}

__device__ __forceinline__ void cp_async16_s(uint32_t dst_smem, const float* src) {
    asm volatile("cp.async.cg.shared.global [%0], [%1], 16;\n" :: "r"(dst_smem), "l"(src));
}

// A-fragment-major float index within a 128x128 tile (R6 layout, verified).
__device__ __forceinline__ int afrag_idx(int m, int k) {
    int rb = m >> 4, m16 = m & 15, lr = m16 & 7, er = m16 >> 3;
    int kstep = k >> 3, k8 = k & 7, la3 = k8 & 3, ec = k8 >> 2;
    return ((((kstep << 3) + rb) * 32 + (lr << 2) + la3) << 2) + er + (ec << 1);
}

// B-fragment-major float index within a 128(out-col)x128(k) tile (R6 layout, verified).
__device__ __forceinline__ int bfrag_idx(int row, int k) {
    int wn = row >> 6, j = (row & 63) >> 3, lr = row & 7;
    int kstep = k >> 3, la3 = k & 3, b1 = ((k & 7) >= 4);
    return (((((kstep << 1) + wn) << 2) + (j >> 1)) * 32 + (lr << 2) + la3) * 4
           + ((j & 1) << 1) + b1;
}

// ---------------------------------------------------------------------------
// Kernel A (R14-verbatim): hidden = relu(x @ Wh^T + bh), tf32-rounded,
//   A-fragment-major scatter. 64x64 tiles -> 448 CTAs of 128 threads.
// ---------------------------------------------------------------------------
__global__ void __launch_bounds__(128)
hidden_gemm(const float* __restrict__ x,
            const float* __restrict__ Wh,
            const float* __restrict__ bh)
{
    __shared__ float As[64][SST];
    __shared__ float Bs[64][SST];

    const int mtile16 = blockIdx.x & 15;      // 0..15 (64-row tiles)
    const int nt64    = blockIdx.x >> 4;      // 0..27 (64-col tiles)
    const int m0 = mtile16 * 64;
    const int n0 = nt64 * 64;

    const int tid  = threadIdx.x;
    const int lane = tid & 31;
    const int warp = tid >> 5;                // 0..3
    const int wm = warp >> 1;                 // 0..1 (32 rows)
    const int wn = warp & 1;                  // 0..1 (32 cols)

    float acc[2][4][4];
    #pragma unroll
    for (int t = 0; t < 2; ++t)
        #pragma unroll
        for (int j = 0; j < 4; ++j)
            #pragma unroll
            for (int q = 0; q < 4; ++q) acc[t][j][q] = 0.f;

    // register staging for the K pipeline (4 A-vec4 + 4 B-vec4 per thread)
    float4 ra[4], rb[4];
    #pragma unroll
    for (int it = 0; it < 4; ++it) {
        int slot = tid + it * 128;            // 0..511
        int r  = slot >> 3;                   // 0..63
        int c4 = (slot & 7) * 4;
        ra[it] = *reinterpret_cast<const float4*>(x  + (size_t)(m0 + r) * DIN + c4);
        rb[it] = *reinterpret_cast<const float4*>(Wh + (size_t)(n0 + r) * DIN + c4);
    }

    for (int k0 = 0; k0 < DIN; k0 += BK) {
        #pragma unroll
        for (int it = 0; it < 4; ++it) {
            int slot = tid + it * 128;
            int r  = slot >> 3;
            int c4 = (slot & 7) * 4;
            As[r][c4 + 0] = __uint_as_float(f2tf32(ra[it].x));
            As[r][c4 + 1] = __uint_as_float(f2tf32(ra[it].y));
            As[r][c4 + 2] = __uint_as_float(f2tf32(ra[it].z));
            As[r][c4 + 3] = __uint_as_float(f2tf32(ra[it].w));
            Bs[r][c4 + 0] = __uint_as_float(f2tf32(rb[it].x));
            Bs[r][c4 + 1] = __uint_as_float(f2tf32(rb[it].y));
            Bs[r][c4 + 2] = __uint_as_float(f2tf32(rb[it].z));
            Bs[r][c4 + 3] = __uint_as_float(f2tf32(rb[it].w));
        }
        __syncthreads();

        // issue next K-slab's LDGs; they drain under the MMA block
        if (k0 + BK < DIN) {
            #pragma unroll
            for (int it = 0; it < 4; ++it) {
                int slot = tid + it * 128;
                int r  = slot >> 3;
                int c4 = (slot & 7) * 4;
                ra[it] = *reinterpret_cast<const float4*>(
                    x + (size_t)(m0 + r) * DIN + k0 + BK + c4);
                rb[it] = *reinterpret_cast<const float4*>(
                    Wh + (size_t)(n0 + r) * DIN + k0 + BK + c4);
            }
        }

        #pragma unroll
        for (int ks = 0; ks < BK; ks += 8) {
            uint32_t a[2][4];
            #pragma unroll
            for (int t = 0; t < 2; ++t) {
                int row = wm * 32 + t * 16 + (lane >> 2);
                int kc  = ks + (lane & 3);
                a[t][0] = __float_as_uint(As[row][kc]);
                a[t][1] = __float_as_uint(As[row + 8][kc]);
                a[t][2] = __float_as_uint(As[row][kc + 4]);
                a[t][3] = __float_as_uint(As[row + 8][kc + 4]);
            }
            #pragma unroll
            for (int j = 0; j < 4; ++j) {
                int col = wn * 32 + j * 8 + (lane >> 2);
                int kc  = ks + (lane & 3);
                uint32_t b[2];
                b[0] = __float_as_uint(Bs[col][kc]);
                b[1] = __float_as_uint(Bs[col][kc + 4]);
                mma_tf32(acc[0][j], a[0], b);
                mma_tf32(acc[1][j], a[1], b);
            }
        }
        __syncthreads();
    }

    // Epilogue: bias + relu + tf32 round -> A-fragment-major scatter.
    const int head  = nt64 >> 1;
    const int kh    = (nt64 & 1) * 64;          // k-offset within head slice
    const int mt128 = mtile16 >> 1;
    const int rbase = (mtile16 & 1) * 64;       // row base within 128-row tile
    float* Hf = g_hfrag + ((size_t)head * MTILES + mt128) * TILE_FLOATS;
    const int lr2  = lane >> 2;
    const int la32 = lane & 3;
    #pragma unroll
    for (int t = 0; t < 2; ++t) {
        #pragma unroll
        for (int j = 0; j < 4; ++j) {
            int klocal = wn * 32 + j * 8 + 2 * la32;   // 0..63
            float b0 = bh[n0 + klocal], b1 = bh[n0 + klocal + 1];
            int kbase = kh + klocal;                   // 0..127
            int mA = rbase + wm * 32 + t * 16 + lr2;   // 0..127
            Hf[afrag_idx(mA,     kbase    )] =
                __uint_as_float(f2tf32(fmaxf(acc[t][j][0] + b0, 0.f)));
            Hf[afrag_idx(mA,     kbase + 1)] =
                __uint_as_float(f2tf32(fmaxf(acc[t][j][1] + b1, 0.f)));
            Hf[afrag_idx(mA + 8, kbase    )] =
                __uint_as_float(f2tf32(fmaxf(acc[t][j][2] + b0, 0.f)));
            Hf[afrag_idx(mA + 8, kbase + 1)] =
                __uint_as_float(f2tf32(fmaxf(acc[t][j][3] + b1, 0.f)));
        }
    }
}

// ---------------------------------------------------------------------------
// Kernel B (R6/R12 verbatim + PDL): 256 threads, warp tile 32x64, one CTA
//   per 128-col N-tile, 8 M-tiles. Independent prologue (B tile + bias) runs
//   BEFORE cudaGridDependencySynchronize(); g_hfrag reads after.
// ---------------------------------------------------------------------------
__global__ void __launch_bounds__(256)
head_gemm(const float* __restrict__ Wheads,
          const float* __restrict__ bheads,
          float* __restrict__ out)
{
    extern __shared__ float smem[];
    float* sB = smem;                         // 16384 floats
    float* sA = smem + TILE_FLOATS;           // 2 x 16384 floats

    const int ntg = blockIdx.x;
    int h = 0;
    #pragma unroll
    for (int i = 1; i < NUM_HEADS; ++i) h += (ntg >= c_tile_start[i]);
    const int ntile = ntg - c_tile_start[h];
    const int p  = c_p[h];
    const int n0 = ntile * 128;

    const float* Bg    = Wheads + (size_t)h * PMAX * DSLICE;
    const float* bias  = bheads + (size_t)h * PMAX;
    float* Og = out + (size_t)c_cum[h] * BROWS;
    const float* Hf = g_hfrag + (size_t)h * MTILES * TILE_FLOATS;

    const int tid  = threadIdx.x;
    const int lane = tid & 31;
    const int warp = tid >> 5;
    const int wm = warp >> 1;   // 0..3
    const int wn = warp & 1;    // 0..1
    const int la3 = lane & 3;
    const int lr  = lane >> 2;

    const uint32_t sA_u = (uint32_t)__cvta_generic_to_shared(sA);

    // ---- independent prologue: B tile -> fragment-major smem, bias hoist
    #pragma unroll
    for (int it = 0; it < 16; ++it) {
        int slot = it * 256 + tid;
        int row = slot >> 5;
        int k4  = (slot & 31) * 4;
        float4 v;
        if (n0 + row < p) {
            v = *reinterpret_cast<const float4*>(Bg + (size_t)(n0 + row) * DSLICE + k4);
        } else {
            v = make_float4(0.f, 0.f, 0.f, 0.f);
        }
        sB[bfrag_idx(row, k4    )] = __uint_as_float(f2tf32(v.x));
        sB[bfrag_idx(row, k4 + 1)] = __uint_as_float(f2tf32(v.y));
        sB[bfrag_idx(row, k4 + 2)] = __uint_as_float(f2tf32(v.z));
        sB[bfrag_idx(row, k4 + 3)] = __uint_as_float(f2tf32(v.w));
    }

    float bs0[8], bs1[8];
    #pragma unroll
    for (int j = 0; j < 8; ++j) {
        int col = n0 + wn * 64 + j * 8 + 2 * la3;
        bs0[j] = (col < p) ? bias[col]     : 0.f;
        bs1[j] = (col < p) ? bias[col + 1] : 0.f;
    }

    // ---- wait for the producer grid (hidden) to fully complete
    cudaGridDependencySynchronize();

    // prefetch A tile 0 (contiguous 64KB; safe to read g_hfrag now)
    #pragma unroll
    for (int it = 0; it < 16; ++it) {
        int fo = (it * 256 + tid) * 4;
        cp_async16_s(sA_u + fo * 4, Hf + fo);
    }
    asm volatile("cp.async.commit_group;\n");

    const float4* sB4 = reinterpret_cast<const float4*>(sB);

    asm volatile("cp.async.wait_group 0;\n" ::: "memory");
    __syncthreads();

    for (int mt = 0; mt < MTILES; ++mt) {
        // prefetch next A tile into the other buffer
        if (mt + 1 < MTILES) {
            const float* src = Hf + (size_t)(mt + 1) * TILE_FLOATS;
            uint32_t dst = sA_u + (uint32_t)(((mt + 1) & 1) ? TILE_FLOATS * 4 : 0);
            #pragma unroll
            for (int it = 0; it < 16; ++it) {
                int fo = (it * 256 + tid) * 4;
                cp_async16_s(dst + fo * 4, src + fo);
            }
            asm volatile("cp.async.commit_group;\n");
        }

        const float4* sA4 = reinterpret_cast<const float4*>(
            sA + (mt & 1) * TILE_FLOATS);

        float acc[2][8][4];
        #pragma unroll
        for (int t = 0; t < 2; ++t)
            #pragma unroll
            for (int j = 0; j < 8; ++j)
                #pragma unroll
                for (int q = 0; q < 4; ++q) acc[t][j][q] = 0.f;

        // register pipeline: fragments for kstep, prefetch kstep+1
        float4 a_cur[2], a_nxt[2], b_cur[2], b_nxt[2], b_cur2[2], b_nxt2[2];
        #pragma unroll
        for (int t = 0; t < 2; ++t)
            a_cur[t] = sA4[(wm * 2 + t) * 32 + lane];
        b_cur[0]  = sB4[(wn * 4 + 0) * 32 + lane];
        b_cur[1]  = sB4[(wn * 4 + 1) * 32 + lane];
        b_cur2[0] = sB4[(wn * 4 + 2) * 32 + lane];
        b_cur2[1] = sB4[(wn * 4 + 3) * 32 + lane];

        #pragma unroll
        for (int ks = 0; ks < 16; ++ks) {
            if (ks + 1 < 16) {
                #pragma unroll
                for (int t = 0; t < 2; ++t)
                    a_nxt[t] = sA4[((ks + 1) * 8 + wm * 2 + t) * 32 + lane];
                b_nxt[0]  = sB4[(((ks + 1) * 2 + wn) * 4 + 0) * 32 + lane];
                b_nxt[1]  = sB4[(((ks + 1) * 2 + wn) * 4 + 1) * 32 + lane];
                b_nxt2[0] = sB4[(((ks + 1) * 2 + wn) * 4 + 2) * 32 + lane];
                b_nxt2[1] = sB4[(((ks + 1) * 2 + wn) * 4 + 3) * 32 + lane];
            }
            const uint32_t* au[2] = {
                reinterpret_cast<const uint32_t*>(&a_cur[0]),
                reinterpret_cast<const uint32_t*>(&a_cur[1])};
            #pragma unroll
            for (int jp = 0; jp < 2; ++jp) {
                const uint32_t* bp = reinterpret_cast<const uint32_t*>(&b_cur[jp]);
                uint32_t b0[2] = {bp[0], bp[1]};
                uint32_t b1[2] = {bp[2], bp[3]};
                mma_tf32(acc[0][jp * 2],     au[0], b0);
                mma_tf32(acc[1][jp * 2],     au[1], b0);
                mma_tf32(acc[0][jp * 2 + 1], au[0], b1);
                mma_tf32(acc[1][jp * 2 + 1], au[1], b1);
            }
            #pragma unroll
            for (int jp = 0; jp < 2; ++jp) {
                const uint32_t* bp = reinterpret_cast<const uint32_t*>(&b_cur2[jp]);
                uint32_t b0[2] = {bp[0], bp[1]};
                uint32_t b1[2] = {bp[2], bp[3]};
                mma_tf32(acc[0][4 + jp * 2],     au[0], b0);
                mma_tf32(acc[1][4 + jp * 2],     au[1], b0);
                mma_tf32(acc[0][4 + jp * 2 + 1], au[0], b1);
                mma_tf32(acc[1][4 + jp * 2 + 1], au[1], b1);
            }
            a_cur[0] = a_nxt[0]; a_cur[1] = a_nxt[1];
            b_cur[0] = b_nxt[0]; b_cur[1] = b_nxt[1];
            b_cur2[0] = b_nxt2[0]; b_cur2[1] = b_nxt2[1];
        }

        // epilogue
        const int m0 = mt * BM;
        #pragma unroll
        for (int t = 0; t < 2; ++t) {
            int row = m0 + wm * 32 + t * 16 + lr;
            #pragma unroll
            for (int j = 0; j < 8; ++j) {
                int col = n0 + wn * 64 + j * 8 + 2 * la3;
                if (col < p) {
                    float2 v0 = make_float2(acc[t][j][0] + bs0[j], acc[t][j][1] + bs1[j]);
                    float2 v1 = make_float2(acc[t][j][2] + bs0[j], acc[t][j][3] + bs1[j]);
                    *reinterpret_cast<float2*>(&Og[(size_t)row * p + col])       = v0;
                    *reinterpret_cast<float2*>(&Og[(size_t)(row + 8) * p + col]) = v1;
                }
            }
        }

        // A(mt+1) ready before next compute; sync also protects buffer reuse
        asm volatile("cp.async.wait_group 0;\n" ::: "memory");
        __syncthreads();
    }
}

} // anonymous namespace

extern "C" void kernel_launch(void* const* d_in, const int* in_sizes, int n_in,
                              void* d_out, int out_size) {
    (void)in_sizes; (void)n_in; (void)out_size;
    const float* x      = (const float*)d_in[0];
    const float* Wh     = (const float*)d_in[1];
    const float* bh     = (const float*)d_in[2];
    const float* Wheads = (const float*)d_in[3];
    const float* bheads = (const float*)d_in[4];
    float* out = (float*)d_out;

    static bool attr_set = false;
    if (!attr_set) {
        cudaFuncSetAttribute(head_gemm,
                             cudaFuncAttributeMaxDynamicSharedMemorySize,
                             (int)HEAD_SMEM_BYTES);
        attr_set = true;
    }

    hidden_gemm<<<16 * (HID / 64), 128>>>(x, Wh, bh);

    // head launched with programmatic stream serialization (PDL): CTAs may
    // begin their independent prologue while hidden drains; the in-kernel
    // grid sync waits for full hidden completion before g_hfrag reads.
    cudaLaunchConfig_t cfg = {};
    cfg.gridDim  = dim3(TOTAL_NTILES, 1, 1);
    cfg.blockDim = dim3(256, 1, 1);
    cfg.dynamicSmemBytes = HEAD_SMEM_BYTES;
    cfg.stream = 0;
    cudaLaunchAttribute attrs[1];
    attrs[0].id = cudaLaunchAttributeProgrammaticStreamSerialization;
    attrs[0].val.programmaticStreamSerializationAllowed = 1;
    cfg.attrs = attrs;
    cfg.numAttrs = 1;
    cudaLaunchKernelEx(&cfg, head_gemm, Wheads, bheads, out);
}

// round 17
// speedup vs baseline: 1.0465x; 1.0241x over previous
#include <cuda_runtime.h>
#include <cstdint>

namespace {

constexpr int NUM_HEADS = 14;
constexpr int BROWS  = 1024;
constexpr int DIN    = 1920;
constexpr int DSLICE = 128;
constexpr int HID    = NUM_HEADS * DSLICE;   // 1792
constexpr int PMAX   = 36928;

constexpr int BM = 128, BK = 32;
constexpr int SST = BK + 4;

__constant__ int c_p[NUM_HEADS] =
    {9280,18496,36928,36928,36928,36928,36928,36928,36928,18496,9280,18496,18496,9280};
__constant__ int c_tile_start[NUM_HEADS] =
    {0,73,218,507,796,1085,1374,1663,1952,2241,2386,2459,2604,2749};
__constant__ int c_cum[NUM_HEADS] =
    {0,9280,27776,64704,101632,138560,175488,212416,249344,286272,304768,314048,332544,351040};

constexpr int TOTAL_NTILES = 2822;
constexpr int MTILES = BROWS / BM;           // 8

constexpr int TILE_FLOATS = BM * DSLICE;     // 16384 floats = 64KB per tile

// head smem: B 64KB + A double-buffer 2x64KB
constexpr size_t HEAD_SMEM_BYTES = (size_t)(3 * TILE_FLOATS) * sizeof(float); // 196608

// hidden activations in A-FRAGMENT-MAJOR 128-row tiles: [head][mtile][16384]
__device__ float g_hfrag[(size_t)NUM_HEADS * MTILES * TILE_FLOATS];

__device__ __forceinline__ uint32_t f2tf32(float f) {
    uint32_t r;
    asm("cvt.rna.tf32.f32 %0, %1;" : "=r"(r) : "f"(f));
    return r;
}

__device__ __forceinline__ void mma_tf32(float* c, const uint32_t* a, const uint32_t* b) {
    asm volatile(
        "mma.sync.aligned.m16n8k8.row.col.f32.tf32.tf32.f32 "
        "{%0,%1,%2,%3}, {%4,%5,%6,%7}, {%8,%9}, {%0,%1,%2,%3};\n"
        : "+f"(c[0]), "+f"(c[1]), "+f"(c[2]), "+f"(c[3])
        : "r"(a[0]), "r"(a[1]), "r"(a[2]), "r"(a[3]),
          "r"(b[0]), "r"(b[1]));
}

__device__ __forceinline__ void cp_async16_s(uint32_t dst_smem, const float* src) {
    asm volatile("cp.async.cg.shared.global [%0], [%1], 16;\n" :: "r"(dst_smem), "l"(src));
}

// A-fragment-major float index within a 128x128 tile (R6 layout, verified).
__device__ __forceinline__ int afrag_idx(int m, int k) {
    int rb = m >> 4, m16 = m & 15, lr = m16 & 7, er = m16 >> 3;
    int kstep = k >> 3, k8 = k & 7, la3 = k8 & 3, ec = k8 >> 2;
    return ((((kstep << 3) + rb) * 32 + (lr << 2) + la3) << 2) + er + (ec << 1);
}

// B-fragment-major float index within a 128(out-col)x128(k) tile (R6 layout, verified).
__device__ __forceinline__ int bfrag_idx(int row, int k) {
    int wn = row >> 6, j = (row & 63) >> 3, lr = row & 7;
    int kstep = k >> 3, la3 = k & 3, b1 = ((k & 7) >= 4);
    return (((((kstep << 1) + wn) << 2) + (j >> 1)) * 32 + (lr << 2) + la3) * 4
           + ((j & 1) << 1) + b1;
}

// ---------------------------------------------------------------------------
// Kernel A (R14-verbatim): hidden = relu(x @ Wh^T + bh), tf32-rounded,
//   A-fragment-major scatter. 64x64 tiles -> 448 CTAs of 128 threads.
// ---------------------------------------------------------------------------
__global__ void __launch_bounds__(128)
hidden_gemm(const float* __restrict__ x,
            const float* __restrict__ Wh,
            const float* __restrict__ bh)
{
    __shared__ float As[64][SST];
    __shared__ float Bs[64][SST];

    const int mtile16 = blockIdx.x & 15;      // 0..15 (64-row tiles)
    const int nt64    = blockIdx.x >> 4;      // 0..27 (64-col tiles)
    const int m0 = mtile16 * 64;
    const int n0 = nt64 * 64;

    const int tid  = threadIdx.x;
    const int lane = tid & 31;
    const int warp = tid >> 5;                // 0..3
    const int wm = warp >> 1;                 // 0..1 (32 rows)
    const int wn = warp & 1;                  // 0..1 (32 cols)

    float acc[2][4][4];
    #pragma unroll
    for (int t = 0; t < 2; ++t)
        #pragma unroll
        for (int j = 0; j < 4; ++j)
            #pragma unroll
            for (int q = 0; q < 4; ++q) acc[t][j][q] = 0.f;

    // register staging for the K pipeline (4 A-vec4 + 4 B-vec4 per thread)
    float4 ra[4], rb[4];
    #pragma unroll
    for (int it = 0; it < 4; ++it) {
        int slot = tid + it * 128;            // 0..511
        int r  = slot >> 3;                   // 0..63
        int c4 = (slot & 7) * 4;
        ra[it] = *reinterpret_cast<const float4*>(x  + (size_t)(m0 + r) * DIN + c4);
        rb[it] = *reinterpret_cast<const float4*>(Wh + (size_t)(n0 + r) * DIN + c4);
    }

    for (int k0 = 0; k0 < DIN; k0 += BK) {
        #pragma unroll
        for (int it = 0; it < 4; ++it) {
            int slot = tid + it * 128;
            int r  = slot >> 3;
            int c4 = (slot & 7) * 4;
            As[r][c4 + 0] = __uint_as_float(f2tf32(ra[it].x));
            As[r][c4 + 1] = __uint_as_float(f2tf32(ra[it].y));
            As[r][c4 + 2] = __uint_as_float(f2tf32(ra[it].z));
            As[r][c4 + 3] = __uint_as_float(f2tf32(ra[it].w));
            Bs[r][c4 + 0] = __uint_as_float(f2tf32(rb[it].x));
            Bs[r][c4 + 1] = __uint_as_float(f2tf32(rb[it].y));
            Bs[r][c4 + 2] = __uint_as_float(f2tf32(rb[it].z));
            Bs[r][c4 + 3] = __uint_as_float(f2tf32(rb[it].w));
        }
        __syncthreads();

        // issue next K-slab's LDGs; they drain under the MMA block
        if (k0 + BK < DIN) {
            #pragma unroll
            for (int it = 0; it < 4; ++it) {
                int slot = tid + it * 128;
                int r  = slot >> 3;
                int c4 = (slot & 7) * 4;
                ra[it] = *reinterpret_cast<const float4*>(
                    x + (size_t)(m0 + r) * DIN + k0 + BK + c4);
                rb[it] = *reinterpret_cast<const float4*>(
                    Wh + (size_t)(n0 + r) * DIN + k0 + BK + c4);
            }
        }

        #pragma unroll
        for (int ks = 0; ks < BK; ks += 8) {
            uint32_t a[2][4];
            #pragma unroll
            for (int t = 0; t < 2; ++t) {
                int row = wm * 32 + t * 16 + (lane >> 2);
                int kc  = ks + (lane & 3);
                a[t][0] = __float_as_uint(As[row][kc]);
                a[t][1] = __float_as_uint(As[row + 8][kc]);
                a[t][2] = __float_as_uint(As[row][kc + 4]);
                a[t][3] = __float_as_uint(As[row + 8][kc + 4]);
            }
            #pragma unroll
            for (int j = 0; j < 4; ++j) {
                int col = wn * 32 + j * 8 + (lane >> 2);
                int kc  = ks + (lane & 3);
                uint32_t b[2];
                b[0] = __float_as_uint(Bs[col][kc]);
                b[1] = __float_as_uint(Bs[col][kc + 4]);
                mma_tf32(acc[0][j], a[0], b);
                mma_tf32(acc[1][j], a[1], b);
            }
        }
        __syncthreads();
    }

    // Epilogue: bias + relu + tf32 round -> A-fragment-major scatter.
    const int head  = nt64 >> 1;
    const int kh    = (nt64 & 1) * 64;          // k-offset within head slice
    const int mt128 = mtile16 >> 1;
    const int rbase = (mtile16 & 1) * 64;       // row base within 128-row tile
    float* Hf = g_hfrag + ((size_t)head * MTILES + mt128) * TILE_FLOATS;
    const int lr2  = lane >> 2;
    const int la32 = lane & 3;
    #pragma unroll
    for (int t = 0; t < 2; ++t) {
        #pragma unroll
        for (int j = 0; j < 4; ++j) {
            int klocal = wn * 32 + j * 8 + 2 * la32;   // 0..63
            float b0 = bh[n0 + klocal], b1 = bh[n0 + klocal + 1];
            int kbase = kh + klocal;                   // 0..127
            int mA = rbase + wm * 32 + t * 16 + lr2;   // 0..127
            Hf[afrag_idx(mA,     kbase    )] =
                __uint_as_float(f2tf32(fmaxf(acc[t][j][0] + b0, 0.f)));
            Hf[afrag_idx(mA,     kbase + 1)] =
                __uint_as_float(f2tf32(fmaxf(acc[t][j][1] + b1, 0.f)));
            Hf[afrag_idx(mA + 8, kbase    )] =
                __uint_as_float(f2tf32(fmaxf(acc[t][j][2] + b0, 0.f)));
            Hf[afrag_idx(mA + 8, kbase + 1)] =
                __uint_as_float(f2tf32(fmaxf(acc[t][j][3] + b1, 0.f)));
        }
    }
}

// ---------------------------------------------------------------------------
// Kernel B (R14 verbatim; grid-sync FIRST, prologue order unchanged):
//   256 threads, warp tile 32x64, one CTA per 128-col N-tile, 8 M-tiles.
//   B fragment-major resident; A tiles cp.async double-buffered; 1-deep
//   register pipeline; one sync per M-tile.
// ---------------------------------------------------------------------------
__global__ void __launch_bounds__(256)
head_gemm(const float* __restrict__ Wheads,
          const float* __restrict__ bheads,
          float* __restrict__ out)
{
    // PDL: wait for the producer grid before ANY memory work. This hides
    // launch latency only; the per-CTA body below is bit-identical to R14.
    cudaGridDependencySynchronize();

    extern __shared__ float smem[];
    float* sB = smem;                         // 16384 floats
    float* sA = smem + TILE_FLOATS;           // 2 x 16384 floats

    const int ntg = blockIdx.x;
    int h = 0;
    #pragma unroll
    for (int i = 1; i < NUM_HEADS; ++i) h += (ntg >= c_tile_start[i]);
    const int ntile = ntg - c_tile_start[h];
    const int p  = c_p[h];
    const int n0 = ntile * 128;

    const float* Bg    = Wheads + (size_t)h * PMAX * DSLICE;
    const float* bias  = bheads + (size_t)h * PMAX;
    float* Og = out + (size_t)c_cum[h] * BROWS;
    const float* Hf = g_hfrag + (size_t)h * MTILES * TILE_FLOATS;

    const int tid  = threadIdx.x;
    const int lane = tid & 31;
    const int warp = tid >> 5;
    const int wm = warp >> 1;   // 0..3
    const int wn = warp & 1;    // 0..1
    const int la3 = lane & 3;
    const int lr  = lane >> 2;

    const uint32_t sA_u = (uint32_t)__cvta_generic_to_shared(sA);

    // prefetch A tile 0 (contiguous 64KB)
    #pragma unroll
    for (int it = 0; it < 16; ++it) {
        int fo = (it * 256 + tid) * 4;
        cp_async16_s(sA_u + fo * 4, Hf + fo);
    }
    asm volatile("cp.async.commit_group;\n");

    // load B tile once -> fragment-major smem
    #pragma unroll
    for (int it = 0; it < 16; ++it) {
        int slot = it * 256 + tid;
        int row = slot >> 5;
        int k4  = (slot & 31) * 4;
        float4 v;
        if (n0 + row < p) {
            v = *reinterpret_cast<const float4*>(Bg + (size_t)(n0 + row) * DSLICE + k4);
        } else {
            v = make_float4(0.f, 0.f, 0.f, 0.f);
        }
        sB[bfrag_idx(row, k4    )] = __uint_as_float(f2tf32(v.x));
        sB[bfrag_idx(row, k4 + 1)] = __uint_as_float(f2tf32(v.y));
        sB[bfrag_idx(row, k4 + 2)] = __uint_as_float(f2tf32(v.z));
        sB[bfrag_idx(row, k4 + 3)] = __uint_as_float(f2tf32(v.w));
    }

    // hoist bias (same columns for every M-tile)
    float bs0[8], bs1[8];
    #pragma unroll
    for (int j = 0; j < 8; ++j) {
        int col = n0 + wn * 64 + j * 8 + 2 * la3;
        bs0[j] = (col < p) ? bias[col]     : 0.f;
        bs1[j] = (col < p) ? bias[col + 1] : 0.f;
    }

    const float4* sB4 = reinterpret_cast<const float4*>(sB);

    asm volatile("cp.async.wait_group 0;\n" ::: "memory");
    __syncthreads();

    for (int mt = 0; mt < MTILES; ++mt) {
        // prefetch next A tile into the other buffer
        if (mt + 1 < MTILES) {
            const float* src = Hf + (size_t)(mt + 1) * TILE_FLOATS;
            uint32_t dst = sA_u + (uint32_t)(((mt + 1) & 1) ? TILE_FLOATS * 4 : 0);
            #pragma unroll
            for (int it = 0; it < 16; ++it) {
                int fo = (it * 256 + tid) * 4;
                cp_async16_s(dst + fo * 4, src + fo);
            }
            asm volatile("cp.async.commit_group;\n");
        }

        const float4* sA4 = reinterpret_cast<const float4*>(
            sA + (mt & 1) * TILE_FLOATS);

        float acc[2][8][4];
        #pragma unroll
        for (int t = 0; t < 2; ++t)
            #pragma unroll
            for (int j = 0; j < 8; ++j)
                #pragma unroll
                for (int q = 0; q < 4; ++q) acc[t][j][q] = 0.f;

        // register pipeline: fragments for kstep, prefetch kstep+1
        float4 a_cur[2], a_nxt[2], b_cur[2], b_nxt[2], b_cur2[2], b_nxt2[2];
        #pragma unroll
        for (int t = 0; t < 2; ++t)
            a_cur[t] = sA4[(wm * 2 + t) * 32 + lane];
        b_cur[0]  = sB4[(wn * 4 + 0) * 32 + lane];
        b_cur[1]  = sB4[(wn * 4 + 1) * 32 + lane];
        b_cur2[0] = sB4[(wn * 4 + 2) * 32 + lane];
        b_cur2[1] = sB4[(wn * 4 + 3) * 32 + lane];

        #pragma unroll
        for (int ks = 0; ks < 16; ++ks) {
            if (ks + 1 < 16) {
                #pragma unroll
                for (int t = 0; t < 2; ++t)
                    a_nxt[t] = sA4[((ks + 1) * 8 + wm * 2 + t) * 32 + lane];
                b_nxt[0]  = sB4[(((ks + 1) * 2 + wn) * 4 + 0) * 32 + lane];
                b_nxt[1]  = sB4[(((ks + 1) * 2 + wn) * 4 + 1) * 32 + lane];
                b_nxt2[0] = sB4[(((ks + 1) * 2 + wn) * 4 + 2) * 32 + lane];
                b_nxt2[1] = sB4[(((ks + 1) * 2 + wn) * 4 + 3) * 32 + lane];
            }
            const uint32_t* au[2] = {
                reinterpret_cast<const uint32_t*>(&a_cur[0]),
                reinterpret_cast<const uint32_t*>(&a_cur[1])};
            #pragma unroll
            for (int jp = 0; jp < 2; ++jp) {
                const uint32_t* bp = reinterpret_cast<const uint32_t*>(&b_cur[jp]);
                uint32_t b0[2] = {bp[0], bp[1]};
                uint32_t b1[2] = {bp[2], bp[3]};
                mma_tf32(acc[0][jp * 2],     au[0], b0);
                mma_tf32(acc[1][jp * 2],     au[1], b0);
                mma_tf32(acc[0][jp * 2 + 1], au[0], b1);
                mma_tf32(acc[1][jp * 2 + 1], au[1], b1);
            }
            #pragma unroll
            for (int jp = 0; jp < 2; ++jp) {
                const uint32_t* bp = reinterpret_cast<const uint32_t*>(&b_cur2[jp]);
                uint32_t b0[2] = {bp[0], bp[1]};
                uint32_t b1[2] = {bp[2], bp[3]};
                mma_tf32(acc[0][4 + jp * 2],     au[0], b0);
                mma_tf32(acc[1][4 + jp * 2],     au[1], b0);
                mma_tf32(acc[0][4 + jp * 2 + 1], au[0], b1);
                mma_tf32(acc[1][4 + jp * 2 + 1], au[1], b1);
            }
            a_cur[0] = a_nxt[0]; a_cur[1] = a_nxt[1];
            b_cur[0] = b_nxt[0]; b_cur[1] = b_nxt[1];
            b_cur2[0] = b_nxt2[0]; b_cur2[1] = b_nxt2[1];
        }

        // epilogue
        const int m0 = mt * BM;
        #pragma unroll
        for (int t = 0; t < 2; ++t) {
            int row = m0 + wm * 32 + t * 16 + lr;
            #pragma unroll
            for (int j = 0; j < 8; ++j) {
                int col = n0 + wn * 64 + j * 8 + 2 * la3;
                if (col < p) {
                    float2 v0 = make_float2(acc[t][j][0] + bs0[j], acc[t][j][1] + bs1[j]);
                    float2 v1 = make_float2(acc[t][j][2] + bs0[j], acc[t][j][3] + bs1[j]);
                    *reinterpret_cast<float2*>(&Og[(size_t)row * p + col])       = v0;
                    *reinterpret_cast<float2*>(&Og[(size_t)(row + 8) * p + col]) = v1;
                }
            }
        }

        // A(mt+1) ready before next compute; sync also protects buffer reuse
        asm volatile("cp.async.wait_group 0;\n" ::: "memory");
        __syncthreads();
    }
}

} // anonymous namespace

extern "C" void kernel_launch(void* const* d_in, const int* in_sizes, int n_in,
                              void* d_out, int out_size) {
    (void)in_sizes; (void)n_in; (void)out_size;
    const float* x      = (const float*)d_in[0];
    const float* Wh     = (const float*)d_in[1];
    const float* bh     = (const float*)d_in[2];
    const float* Wheads = (const float*)d_in[3];
    const float* bheads = (const float*)d_in[4];
    float* out = (float*)d_out;

    static bool attr_set = false;
    if (!attr_set) {
        cudaFuncSetAttribute(head_gemm,
                             cudaFuncAttributeMaxDynamicSharedMemorySize,
                             (int)HEAD_SMEM_BYTES);
        attr_set = true;
    }

    hidden_gemm<<<16 * (HID / 64), 128>>>(x, Wh, bh);

    // PDL launch: head CTAs may be scheduled while hidden drains; the
    // grid-sync at the top of head_gemm waits for hidden completion.
    cudaLaunchConfig_t cfg = {};
    cfg.gridDim  = dim3(TOTAL_NTILES, 1, 1);
    cfg.blockDim = dim3(256, 1, 1);
    cfg.dynamicSmemBytes = HEAD_SMEM_BYTES;
    cfg.stream = 0;
    cudaLaunchAttribute attrs[1];
    attrs[0].id = cudaLaunchAttributeProgrammaticStreamSerialization;
    attrs[0].val.programmaticStreamSerializationAllowed = 1;
    cfg.attrs = attrs;
    cfg.numAttrs = 1;
    cudaLaunchKernelEx(&cfg, head_gemm, Wheads, bheads, out);
}